// round 2
// baseline (speedup 1.0000x reference)
#include <cuda_runtime.h>

// ---------------------------------------------------------------------------
// NonLocalMSA fp32 pipeline, round 2: packed f32x2 FMA + occupancy fixes.
// K1 qkv+dw fused | K2 sim partials (split K) | K3 softmax | K4 attn@V (split
// output chunks) | K5 proj.
// ---------------------------------------------------------------------------

#define HW 65536  // 256*256
typedef unsigned long long ull;

__device__ __forceinline__ ull ffma2(ull a, ull b, ull c) {
    ull d; asm("fma.rn.f32x2 %0, %1, %2, %3;" : "=l"(d) : "l"(a), "l"(b), "l"(c));
    return d;
}
__device__ __forceinline__ ull fadd2(ull a, ull b) {
    ull d; asm("add.rn.f32x2 %0, %1, %2;" : "=l"(d) : "l"(a), "l"(b));
    return d;
}
__device__ __forceinline__ ull fdup(float v) {
    ull d; asm("mov.b64 %0, {%1, %1};" : "=l"(d) : "f"(v));
    return d;
}

// Scratch (device globals: allocation-free rule)
__device__ float g_qkv[16ull * 192 * 256 * 256];  // 805 MB
__device__ float g_av [16ull *  64 * 256 * 256];  // 268 MB
__device__ float g_sim[1024ull * 64 * 64];        // 16 MB (8 partials per (b,h))
__device__ float g_attn[128ull * 64 * 64];        // 2 MB

// ===========================================================================
// K1: fused 1x1 qkv projection + 3x3 depthwise conv.
// ===========================================================================
#define HPAD 328
#define OC 48

extern __shared__ float dsm[];

__global__ __launch_bounds__(512) void k1_qkv_dw(
    const float* __restrict__ x, const float* __restrict__ wqkv,
    const float* __restrict__ wdw)
{
    ull*   sdupw = (ull*)dsm;                 // [64 c][OC] dup'd weights
    float* sx    = (float*)(sdupw + 64 * OC); // [64][HPAD]
    float* sq    = sx + 64 * HPAD;            // [OC][HPAD]
    float* sdw   = sq + OC * HPAD;            // [OC][9]

    const int b = blockIdx.z, ty = blockIdx.y, tx = blockIdx.x;
    const int tid = threadIdx.x;
    const float* xb = x + (size_t)b * 64 * HW;

    // x tile with 1-halo, zero padded (qkv(0)=0 since no bias -> exact)
    for (int idx = tid; idx < 64 * 324; idx += 512) {
        int c = idx / 324, p = idx - c * 324;
        int iy = p / 18, ix = p - iy * 18;
        int gy = ty * 16 - 1 + iy, gx = tx * 16 - 1 + ix;
        float v = 0.f;
        if ((unsigned)gy < 256u && (unsigned)gx < 256u)
            v = xb[c * HW + gy * 256 + gx];
        sx[c * HPAD + p] = v;
    }

    for (int ocb = 0; ocb < 4; ocb++) {
        const int o0 = ocb * OC;
        __syncthreads();  // protect sdupw/sq reuse (also orders sx after load)
        for (int idx = tid; idx < OC * 64; idx += 512) {
            int o = idx >> 6, c = idx & 63;
            sdupw[c * OC + o] = fdup(wqkv[(o0 + o) * 64 + c]);
        }
        for (int idx = tid; idx < OC * 9; idx += 512)
            sdw[idx] = wdw[(o0 + idx / 9) * 9 + idx % 9];
        __syncthreads();

        // 1x1 over halo tile: 12 o-groups x 81 p-groups, f32x2 4x4 tile
        for (int u = tid; u < 12 * 81; u += 512) {
            int og = u / 81, pg = u - og * 81;
            int ob = og * 4, pb = pg * 4;
            ull a00=0,a01=0, a10=0,a11=0, a20=0,a21=0, a30=0,a31=0;
            #pragma unroll 8
            for (int c = 0; c < 64; c++) {
                const ulonglong2* wr = (const ulonglong2*)(sdupw + c * OC + ob);
                ulonglong2 wA = wr[0], wB = wr[1];
                ulonglong2 xv = *(const ulonglong2*)&sx[c * HPAD + pb];
                a00 = ffma2(wA.x, xv.x, a00); a01 = ffma2(wA.x, xv.y, a01);
                a10 = ffma2(wA.y, xv.x, a10); a11 = ffma2(wA.y, xv.y, a11);
                a20 = ffma2(wB.x, xv.x, a20); a21 = ffma2(wB.x, xv.y, a21);
                a30 = ffma2(wB.y, xv.x, a30); a31 = ffma2(wB.y, xv.y, a31);
            }
            ulonglong2 s;
            s.x=a00; s.y=a01; *(ulonglong2*)&sq[(ob+0) * HPAD + pb] = s;
            s.x=a10; s.y=a11; *(ulonglong2*)&sq[(ob+1) * HPAD + pb] = s;
            s.x=a20; s.y=a21; *(ulonglong2*)&sq[(ob+2) * HPAD + pb] = s;
            s.x=a30; s.y=a31; *(ulonglong2*)&sq[(ob+3) * HPAD + pb] = s;
        }
        __syncthreads();

        // depthwise 3x3 on interior; write to g_qkv
        for (int idx = tid; idx < OC * 256; idx += 512) {
            int o = idx >> 8, p = idx & 255;
            int iy = p >> 4, ix = p & 15;
            const float* q = &sq[o * HPAD + iy * 18 + ix];
            const float* d = &sdw[o * 9];
            float acc = d[0]*q[0]  + d[1]*q[1]  + d[2]*q[2]
                      + d[3]*q[18] + d[4]*q[19] + d[5]*q[20]
                      + d[6]*q[36] + d[7]*q[37] + d[8]*q[38];
            int gy = ty * 16 + iy, gx = tx * 16 + ix;
            g_qkv[(((size_t)b * 192 + o0 + o) * 256 + gy) * 256 + gx] = acc;
        }
    }
}

// ===========================================================================
// K2: sim partials. Block = (b,h,r,half). C[64,64] += A[64,1024] * B^T.
// A is stored dup'd in smem so f32x2 needs no register packing.
// ===========================================================================
__global__ __launch_bounds__(256) void k2_sim()
{
    ull*   Asd = (ull*)dsm;               // [64 k][68] dup'd q
    float* Bs  = (float*)(Asd + 64 * 68); // [64 k][68]
    const int blk = blockIdx.x;
    const int half = blk & 1, r = (blk >> 1) & 3, h = (blk >> 3) & 7, b = blk >> 6;
    const int tid = threadIdx.x, ti = tid >> 4, tj = tid & 15;
    const int yoff = h * 4 + r;

    const float* qbase = g_qkv + (size_t)b * 192 * HW;
    const float* kbase = qbase + (size_t)64 * HW;

    ull c00=0,c01=0, c10=0,c11=0, c20=0,c21=0, c30=0,c31=0;

    for (int kc = half * 16; kc < half * 16 + 16; kc++) {
        __syncthreads();
        for (int idx = tid; idx < 4096; idx += 256) {
            int t = idx >> 6, kl = idx & 63;
            int chp = kl >> 5, col = kl & 31;
            int y = (t >> 3) * 32 + yoff;
            int xx = (t & 7) * 32 + col;
            size_t off = (size_t)(kc * 2 + chp) * HW + y * 256 + xx;
            Asd[kl * 68 + t] = fdup(qbase[off]);
            Bs [kl * 68 + t] = kbase[off];
        }
        __syncthreads();
        #pragma unroll 8
        for (int kk = 0; kk < 64; kk++) {
            ulonglong2 aA = *(const ulonglong2*)(Asd + kk * 68 + ti * 4);
            ulonglong2 aB = *(const ulonglong2*)(Asd + kk * 68 + ti * 4 + 2);
            ulonglong2 bv = *(const ulonglong2*)&Bs[kk * 68 + tj * 4];
            c00 = ffma2(aA.x, bv.x, c00); c01 = ffma2(aA.x, bv.y, c01);
            c10 = ffma2(aA.y, bv.x, c10); c11 = ffma2(aA.y, bv.y, c11);
            c20 = ffma2(aB.x, bv.x, c20); c21 = ffma2(aB.x, bv.y, c21);
            c30 = ffma2(aB.y, bv.x, c30); c31 = ffma2(aB.y, bv.y, c31);
        }
    }
    float* so = g_sim + (size_t)blk * 4096;
    ulonglong2 s;
    s.x=c00; s.y=c01; *(ulonglong2*)&so[(ti*4+0)*64 + tj*4] = s;
    s.x=c10; s.y=c11; *(ulonglong2*)&so[(ti*4+1)*64 + tj*4] = s;
    s.x=c20; s.y=c21; *(ulonglong2*)&so[(ti*4+2)*64 + tj*4] = s;
    s.x=c30; s.y=c31; *(ulonglong2*)&so[(ti*4+3)*64 + tj*4] = s;
}

// ===========================================================================
// K3: softmax over j(64): attn = softmax(scale * sum of 8 partials + pos_emb)
// ===========================================================================
__global__ __launch_bounds__(128) void k3_softmax(const float* __restrict__ pos)
{
    const float SCALE = 0.011048543456039806f;  // 8192^-0.5
    int row = blockIdx.x * 4 + (threadIdx.x >> 5);
    int lane = threadIdx.x & 31;
    int bh = row >> 6, i = row & 63;
    const float* s0 = g_sim + (size_t)bh * 8 * 4096 + i * 64;
    const float* pe = pos + (bh & 7) * 4096 + i * 64;
    float acc1 = 0.f, acc2 = 0.f;
    #pragma unroll
    for (int p = 0; p < 8; p++) {
        acc1 += s0[p * 4096 + lane];
        acc2 += s0[p * 4096 + lane + 32];
    }
    float v1 = SCALE * acc1 + pe[lane];
    float v2 = SCALE * acc2 + pe[lane + 32];
    float m = fmaxf(v1, v2);
    #pragma unroll
    for (int o = 16; o; o >>= 1) m = fmaxf(m, __shfl_xor_sync(0xffffffffu, m, o));
    float e1 = __expf(v1 - m), e2 = __expf(v2 - m);
    float s = e1 + e2;
    #pragma unroll
    for (int o = 16; o; o >>= 1) s += __shfl_xor_sync(0xffffffffu, s, o);
    float inv = 1.f / s;
    g_attn[(size_t)row * 64 + lane]      = e1 * inv;
    g_attn[(size_t)row * 64 + lane + 32] = e2 * inv;
}

// ===========================================================================
// K4: out = attn @ V. Block = (b,h,r,cg): 8 of the 32 (2ch x 32col) chunks.
// ===========================================================================
__global__ __launch_bounds__(256) void k4_av()
{
    ull*   Atd = (ull*)dsm;               // [64 j][68] dup'd attn^T
    float* Vs  = (float*)(Atd + 64 * 68); // [64 j][68]
    const int blk = blockIdx.x;
    const int cg = blk & 3, r = (blk >> 2) & 3, h = (blk >> 4) & 7, b = blk >> 7;
    const int tid = threadIdx.x, ti = tid >> 4, tj = tid & 15;
    const int yoff = h * 4 + r;

    const float* ap = g_attn + (size_t)(b * 8 + h) * 4096;
    for (int idx = tid; idx < 4096; idx += 256) {
        int t = idx >> 6, j = idx & 63;
        Atd[j * 68 + t] = fdup(ap[t * 64 + j]);
    }
    const float* vbase = g_qkv + ((size_t)b * 192 + 128) * HW;
    float* ob = g_av + (size_t)b * 64 * HW;

    for (int cp = cg * 8; cp < cg * 8 + 8; cp++) {
        __syncthreads();  // protects Atd (first iter) and Vs (later iters)
        for (int idx = tid; idx < 4096; idx += 256) {
            int j = idx >> 6, kl = idx & 63;
            int chp = kl >> 5, col = kl & 31;
            int y = (j >> 3) * 32 + yoff;
            int xx = (j & 7) * 32 + col;
            Vs[j * 68 + kl] = vbase[(size_t)(cp * 2 + chp) * HW + y * 256 + xx];
        }
        __syncthreads();
        ull c00=0,c01=0, c10=0,c11=0, c20=0,c21=0, c30=0,c31=0;
        #pragma unroll 8
        for (int kk = 0; kk < 64; kk++) {
            ulonglong2 aA = *(const ulonglong2*)(Atd + kk * 68 + ti * 4);
            ulonglong2 aB = *(const ulonglong2*)(Atd + kk * 68 + ti * 4 + 2);
            ulonglong2 vv = *(const ulonglong2*)&Vs[kk * 68 + tj * 4];
            c00 = ffma2(aA.x, vv.x, c00); c01 = ffma2(aA.x, vv.y, c01);
            c10 = ffma2(aA.y, vv.x, c10); c11 = ffma2(aA.y, vv.y, c11);
            c20 = ffma2(aB.x, vv.x, c20); c21 = ffma2(aB.x, vv.y, c21);
            c30 = ffma2(aB.y, vv.x, c30); c31 = ffma2(aB.y, vv.y, c31);
        }
        int cc0 = tj * 4, chp = cc0 >> 5, col0 = cc0 & 31;
        size_t cbase = (size_t)(cp * 2 + chp) * HW;
        ull rows[8] = {c00,c01, c10,c11, c20,c21, c30,c31};
        #pragma unroll
        for (int ii = 0; ii < 4; ii++) {
            int t = ti * 4 + ii;
            int y = (t >> 3) * 32 + yoff;
            int xx = (t & 7) * 32 + col0;
            ulonglong2 s; s.x = rows[ii*2]; s.y = rows[ii*2+1];
            *(ulonglong2*)&ob[cbase + y * 256 + xx] = s;
        }
    }
}

// ===========================================================================
// K5: 1x1 projection + bias. Block = 64 spatial positions; [64x64] GEMM.
// ===========================================================================
__global__ __launch_bounds__(256) void k5_proj(
    const float* __restrict__ wp, const float* __restrict__ bp,
    float* __restrict__ out)
{
    ull*   Wsd = (ull*)dsm;               // [64 c][68] dup'd W^T
    float* Xs  = (float*)(Wsd + 64 * 68); // [64 c][68]
    const int blk = blockIdx.x;           // 16384 = 16 b * 256 y * 4 xq
    const int b = blk >> 10;
    const int rem = blk & 1023;
    const int y = rem >> 2, x0 = (rem & 3) << 6;
    const int tid = threadIdx.x, ti = tid >> 4, tj = tid & 15;

    const float* ib = g_av + (size_t)b * 64 * HW + y * 256 + x0;
    for (int idx = tid; idx < 4096; idx += 256) {
        int o = idx >> 6, c = idx & 63;
        Wsd[c * 68 + o] = fdup(wp[o * 64 + c]);
    }
    for (int idx = tid; idx < 4096; idx += 256) {
        int c = idx >> 6, p = idx & 63;
        Xs[c * 68 + p] = ib[(size_t)c * HW + p];
    }
    __syncthreads();
    ull c00=0,c01=0, c10=0,c11=0, c20=0,c21=0, c30=0,c31=0;
    #pragma unroll 8
    for (int c = 0; c < 64; c++) {
        ulonglong2 wA = *(const ulonglong2*)(Wsd + c * 68 + ti * 4);
        ulonglong2 wB = *(const ulonglong2*)(Wsd + c * 68 + ti * 4 + 2);
        ulonglong2 xv = *(const ulonglong2*)&Xs[c * 68 + tj * 4];
        c00 = ffma2(wA.x, xv.x, c00); c01 = ffma2(wA.x, xv.y, c01);
        c10 = ffma2(wA.y, xv.x, c10); c11 = ffma2(wA.y, xv.y, c11);
        c20 = ffma2(wB.x, xv.x, c20); c21 = ffma2(wB.x, xv.y, c21);
        c30 = ffma2(wB.y, xv.x, c30); c31 = ffma2(wB.y, xv.y, c31);
    }
    float* op = out + (size_t)b * 64 * HW + y * 256 + x0 + tj * 4;
    ull b0 = fdup(bp[ti*4+0]), b1 = fdup(bp[ti*4+1]);
    ull b2 = fdup(bp[ti*4+2]), b3 = fdup(bp[ti*4+3]);
    ulonglong2 s;
    s.x=fadd2(c00,b0); s.y=fadd2(c01,b0); *(ulonglong2*)&op[(size_t)(ti*4+0) * HW] = s;
    s.x=fadd2(c10,b1); s.y=fadd2(c11,b1); *(ulonglong2*)&op[(size_t)(ti*4+1) * HW] = s;
    s.x=fadd2(c20,b2); s.y=fadd2(c21,b2); *(ulonglong2*)&op[(size_t)(ti*4+2) * HW] = s;
    s.x=fadd2(c30,b3); s.y=fadd2(c31,b3); *(ulonglong2*)&op[(size_t)(ti*4+3) * HW] = s;
}

// ===========================================================================
extern "C" void kernel_launch(void* const* d_in, const int* in_sizes, int n_in,
                              void* d_out, int out_size)
{
    const float* x     = (const float*)d_in[0];
    const float* wqkv  = (const float*)d_in[1];
    const float* wdw   = (const float*)d_in[2];
    const float* wproj = (const float*)d_in[3];
    const float* bproj = (const float*)d_in[4];
    const float* pos   = (const float*)d_in[5];
    float* out = (float*)d_out;

    const int smem1 = 64*OC*8 + (64*HPAD + OC*HPAD + OC*9) * 4;  // 173,248 B
    const int smemG = 64*68*8 + 64*68*4;                          // 52,224 B
    cudaFuncSetAttribute(k1_qkv_dw, cudaFuncAttributeMaxDynamicSharedMemorySize, smem1);
    cudaFuncSetAttribute(k2_sim,    cudaFuncAttributeMaxDynamicSharedMemorySize, smemG);
    cudaFuncSetAttribute(k4_av,     cudaFuncAttributeMaxDynamicSharedMemorySize, smemG);
    cudaFuncSetAttribute(k5_proj,   cudaFuncAttributeMaxDynamicSharedMemorySize, smemG);

    k1_qkv_dw<<<dim3(16, 16, 16), 512, smem1>>>(x, wqkv, wdw);
    k2_sim<<<1024, 256, smemG>>>();
    k3_softmax<<<2048, 128>>>(pos);
    k4_av<<<2048, 256, smemG>>>();
    k5_proj<<<16384, 256, smemG>>>(wproj, bproj, out);
}

// round 6
// speedup vs baseline: 1.4484x; 1.4484x over previous
#include <cuda_runtime.h>

// ---------------------------------------------------------------------------
// NonLocalMSA fp32, round 6 (= round 4 kernel; two consecutive infra failures).
// R3 structure with K4 Vs-transpose bug fixed.
// K1 qkv+dw fused | K2 sim (K-split) | K3 softmax | K4 attn@V | K5 proj
// ---------------------------------------------------------------------------

#define HW 65536  // 256*256

__device__ float g_qkv[16ull * 192 * 256 * 256];  // 805 MB
__device__ float g_av [16ull *  64 * 256 * 256];  // 268 MB
__device__ float g_sim[1024ull * 64 * 64];        // 16 MB (8 partials per (b,h))
__device__ float g_attn[128ull * 64 * 64];        // 2 MB

// ===========================================================================
// K1: fused 1x1 qkv projection + 3x3 depthwise conv. 16x16 tile, halo 18x18.
// 1x1 inner loop: 8-out x 4-pos register tile, [c][o] weight layout.
// ===========================================================================
#define HPAD 328   // 18*18=324 padded to 328 (82 float4)
#define OC 48

extern __shared__ float dsm[];

__global__ __launch_bounds__(512) void k1_qkv_dw(
    const float* __restrict__ x, const float* __restrict__ wqkv,
    const float* __restrict__ wdw)
{
    float* sx  = dsm;                 // [64][HPAD]
    float* sq  = sx + 64 * HPAD;      // [OC][HPAD]
    float* sw  = sq + OC * HPAD;      // [64 c][OC]  (c-major, o contiguous)
    float* sdw = sw + 64 * OC;        // [OC][9]

    const int b = blockIdx.z, ty = blockIdx.y, tx = blockIdx.x;
    const int tid = threadIdx.x;
    const float* xb = x + (size_t)b * 64 * HW;

    // x tile with 1-halo, zero padded (1x1 has no bias -> qkv(0)=0 -> exact)
    for (int idx = tid; idx < 64 * 324; idx += 512) {
        int c = idx / 324, p = idx - c * 324;
        int iy = p / 18, ix = p - iy * 18;
        int gy = ty * 16 - 1 + iy, gx = tx * 16 - 1 + ix;
        float v = 0.f;
        if ((unsigned)gy < 256u && (unsigned)gx < 256u)
            v = xb[c * HW + gy * 256 + gx];
        sx[c * HPAD + p] = v;
    }

    const float4* sx4 = (const float4*)sx;
    const float4* sw4 = (const float4*)sw;

    for (int ocb = 0; ocb < 4; ocb++) {
        const int o0 = ocb * OC;
        __syncthreads();  // protect sw/sq reuse (also orders sx after load)
        for (int idx = tid; idx < OC * 64; idx += 512) {
            int o = idx >> 6, c = idx & 63;          // coalesced gmem read in c
            sw[c * OC + o] = wqkv[(o0 + o) * 64 + c];
        }
        for (int idx = tid; idx < OC * 9; idx += 512)
            sdw[idx] = wdw[(o0 + idx / 9) * 9 + idx % 9];
        __syncthreads();

        // 1x1 over halo tile: 6 o-groups(8) x 81 p-groups(4) = 486 units
        if (tid < 486) {
            int og = tid / 81, pg = tid - og * 81;
            int ob = og * 8, pb = pg * 4;
            float a0x=0,a0y=0,a0z=0,a0w=0, a1x=0,a1y=0,a1z=0,a1w=0;
            float a2x=0,a2y=0,a2z=0,a2w=0, a3x=0,a3y=0,a3z=0,a3w=0;
            float a4x=0,a4y=0,a4z=0,a4w=0, a5x=0,a5y=0,a5z=0,a5w=0;
            float a6x=0,a6y=0,a6z=0,a6w=0, a7x=0,a7y=0,a7z=0,a7w=0;
            #pragma unroll 8
            for (int c = 0; c < 64; c++) {
                float4 w0 = sw4[c * 12 + og * 2];
                float4 w1 = sw4[c * 12 + og * 2 + 1];
                float4 xv = sx4[c * 82 + pg];
                a0x += w0.x*xv.x; a0y += w0.x*xv.y; a0z += w0.x*xv.z; a0w += w0.x*xv.w;
                a1x += w0.y*xv.x; a1y += w0.y*xv.y; a1z += w0.y*xv.z; a1w += w0.y*xv.w;
                a2x += w0.z*xv.x; a2y += w0.z*xv.y; a2z += w0.z*xv.z; a2w += w0.z*xv.w;
                a3x += w0.w*xv.x; a3y += w0.w*xv.y; a3z += w0.w*xv.z; a3w += w0.w*xv.w;
                a4x += w1.x*xv.x; a4y += w1.x*xv.y; a4z += w1.x*xv.z; a4w += w1.x*xv.w;
                a5x += w1.y*xv.x; a5y += w1.y*xv.y; a5z += w1.y*xv.z; a5w += w1.y*xv.w;
                a6x += w1.z*xv.x; a6y += w1.z*xv.y; a6z += w1.z*xv.z; a6w += w1.z*xv.w;
                a7x += w1.w*xv.x; a7y += w1.w*xv.y; a7z += w1.w*xv.z; a7w += w1.w*xv.w;
            }
            *(float4*)&sq[(ob+0) * HPAD + pb] = make_float4(a0x,a0y,a0z,a0w);
            *(float4*)&sq[(ob+1) * HPAD + pb] = make_float4(a1x,a1y,a1z,a1w);
            *(float4*)&sq[(ob+2) * HPAD + pb] = make_float4(a2x,a2y,a2z,a2w);
            *(float4*)&sq[(ob+3) * HPAD + pb] = make_float4(a3x,a3y,a3z,a3w);
            *(float4*)&sq[(ob+4) * HPAD + pb] = make_float4(a4x,a4y,a4z,a4w);
            *(float4*)&sq[(ob+5) * HPAD + pb] = make_float4(a5x,a5y,a5z,a5w);
            *(float4*)&sq[(ob+6) * HPAD + pb] = make_float4(a6x,a6y,a6z,a6w);
            *(float4*)&sq[(ob+7) * HPAD + pb] = make_float4(a7x,a7y,a7z,a7w);
        }
        __syncthreads();

        // depthwise 3x3 on interior; write to g_qkv
        for (int idx = tid; idx < OC * 256; idx += 512) {
            int o = idx >> 8, p = idx & 255;
            int iy = p >> 4, ix = p & 15;
            const float* q = &sq[o * HPAD + iy * 18 + ix];
            const float* d = &sdw[o * 9];
            float acc = d[0]*q[0]  + d[1]*q[1]  + d[2]*q[2]
                      + d[3]*q[18] + d[4]*q[19] + d[5]*q[20]
                      + d[6]*q[36] + d[7]*q[37] + d[8]*q[38];
            int gy = ty * 16 + iy, gx = tx * 16 + ix;
            g_qkv[(((size_t)b * 192 + o0 + o) * 256 + gy) * 256 + gx] = acc;
        }
    }
}

// ===========================================================================
// K2: sim partials. Block=(b,h,r,half): C[64,64] += A[64,1024]*B^T.
// Software pipeline: prefetch next chunk to registers during compute.
// smem layout: As/Bs[k][t]  (row = k element, col = token)
// ===========================================================================
__global__ __launch_bounds__(256) void k2_sim()
{
    __shared__ float As[64 * 68];  // [kl][t]
    __shared__ float Bs[64 * 68];
    const int blk = blockIdx.x;
    const int half = blk & 1, r = (blk >> 1) & 3, h = (blk >> 3) & 7, b = blk >> 6;
    const int tid = threadIdx.x, ti = tid >> 4, tj = tid & 15;
    const int yoff = h * 4 + r;

    const float* qbase = g_qkv + (size_t)b * 192 * HW;
    const float* kbase = qbase + (size_t)64 * HW;
    const float4* As4 = (const float4*)As;
    const float4* Bs4 = (const float4*)Bs;

    // per-thread load slots: idx = tid + p*256 -> t = idx>>6, kl = idx&63
    int tt[16], kk_[16];
    size_t goff[16];
    #pragma unroll
    for (int p = 0; p < 16; p++) {
        int idx = tid + p * 256;
        int t = idx >> 6, kl = idx & 63;
        int chp = kl >> 5, col = kl & 31;
        int y = (t >> 3) * 32 + yoff, xx = (t & 7) * 32 + col;
        tt[p] = t; kk_[p] = kl;
        goff[p] = (size_t)chp * HW + y * 256 + xx;  // + kc*2*HW added per chunk
    }

    const int kc0 = half * 16;
    float pa[16], pb[16];
    #pragma unroll
    for (int p = 0; p < 16; p++) {
        size_t o = (size_t)kc0 * 2 * HW + goff[p];
        pa[p] = qbase[o]; pb[p] = kbase[o];
    }

    float c00=0,c01=0,c02=0,c03=0, c10=0,c11=0,c12=0,c13=0;
    float c20=0,c21=0,c22=0,c23=0, c30=0,c31=0,c32=0,c33=0;

    for (int kc = kc0; kc < kc0 + 16; kc++) {
        __syncthreads();  // readers of As/Bs done
        #pragma unroll
        for (int p = 0; p < 16; p++) {
            As[kk_[p] * 68 + tt[p]] = pa[p];   // row = k element, col = token
            Bs[kk_[p] * 68 + tt[p]] = pb[p];
        }
        __syncthreads();
        if (kc + 1 < kc0 + 16) {
            #pragma unroll
            for (int p = 0; p < 16; p++) {
                size_t o = (size_t)(kc + 1) * 2 * HW + goff[p];
                pa[p] = qbase[o]; pb[p] = kbase[o];
            }
        }
        #pragma unroll 8
        for (int kk = 0; kk < 64; kk++) {
            float4 av = As4[kk * 17 + ti];
            float4 bv = Bs4[kk * 17 + tj];
            c00 += av.x*bv.x; c01 += av.x*bv.y; c02 += av.x*bv.z; c03 += av.x*bv.w;
            c10 += av.y*bv.x; c11 += av.y*bv.y; c12 += av.y*bv.z; c13 += av.y*bv.w;
            c20 += av.z*bv.x; c21 += av.z*bv.y; c22 += av.z*bv.z; c23 += av.z*bv.w;
            c30 += av.w*bv.x; c31 += av.w*bv.y; c32 += av.w*bv.z; c33 += av.w*bv.w;
        }
    }
    float* so = g_sim + (size_t)blk * 4096;
    *(float4*)&so[(ti*4+0)*64 + tj*4] = make_float4(c00,c01,c02,c03);
    *(float4*)&so[(ti*4+1)*64 + tj*4] = make_float4(c10,c11,c12,c13);
    *(float4*)&so[(ti*4+2)*64 + tj*4] = make_float4(c20,c21,c22,c23);
    *(float4*)&so[(ti*4+3)*64 + tj*4] = make_float4(c30,c31,c32,c33);
}

// ===========================================================================
// K3: softmax over j(64) of scale * (sum of 8 partials) + pos_emb
// ===========================================================================
__global__ __launch_bounds__(128) void k3_softmax(const float* __restrict__ pos)
{
    const float SCALE = 0.011048543456039806f;  // 8192^-0.5
    int row = blockIdx.x * 4 + (threadIdx.x >> 5);
    int lane = threadIdx.x & 31;
    int bh = row >> 6, i = row & 63;
    const float* s0 = g_sim + (size_t)bh * 8 * 4096 + i * 64;
    const float* pe = pos + (bh & 7) * 4096 + i * 64;
    float acc1 = 0.f, acc2 = 0.f;
    #pragma unroll
    for (int p = 0; p < 8; p++) {
        acc1 += s0[p * 4096 + lane];
        acc2 += s0[p * 4096 + lane + 32];
    }
    float v1 = SCALE * acc1 + pe[lane];
    float v2 = SCALE * acc2 + pe[lane + 32];
    float m = fmaxf(v1, v2);
    #pragma unroll
    for (int o = 16; o; o >>= 1) m = fmaxf(m, __shfl_xor_sync(0xffffffffu, m, o));
    float e1 = __expf(v1 - m), e2 = __expf(v2 - m);
    float s = e1 + e2;
    #pragma unroll
    for (int o = 16; o; o >>= 1) s += __shfl_xor_sync(0xffffffffu, s, o);
    float inv = 1.f / s;
    g_attn[(size_t)row * 64 + lane]      = e1 * inv;
    g_attn[(size_t)row * 64 + lane + 32] = e2 * inv;
}

// ===========================================================================
// K4: out = attn @ V. Block=(b,h,r,cg): 16 of 32 (2ch x 32col) chunks.
// Vs loads software-pipelined through registers.
// smem layout: At[j][t], Vs[j][cc]  (row = j token == contraction dim)
// ===========================================================================
__global__ __launch_bounds__(256) void k4_av()
{
    __shared__ float At[64 * 68];  // [j][t]
    __shared__ float Vs[64 * 68];  // [j][cc]
    const int blk = blockIdx.x;
    const int cg = blk & 1, r = (blk >> 1) & 3, h = (blk >> 3) & 7, b = blk >> 6;
    const int tid = threadIdx.x, ti = tid >> 4, tj = tid & 15;
    const int yoff = h * 4 + r;

    const float* ap = g_attn + (size_t)(b * 8 + h) * 4096;
    for (int idx = tid; idx < 4096; idx += 256) {
        int t = idx >> 6, j = idx & 63;
        At[j * 68 + t] = ap[t * 64 + j];
    }
    const float* vbase = g_qkv + ((size_t)b * 192 + 128) * HW;
    float* ob = g_av + (size_t)b * 64 * HW;
    const float4* At4 = (const float4*)At;
    const float4* Vs4 = (const float4*)Vs;

    // slot p: j = token index (row of Vs), kl = channel-chunk element (col)
    int jj[16], kk_[16];
    size_t goff[16];
    #pragma unroll
    for (int p = 0; p < 16; p++) {
        int idx = tid + p * 256;
        int j = idx >> 6, kl = idx & 63;
        int chp = kl >> 5, col = kl & 31;
        int y = (j >> 3) * 32 + yoff, xx = (j & 7) * 32 + col;
        jj[p] = j; kk_[p] = kl;
        goff[p] = (size_t)chp * HW + y * 256 + xx;
    }

    const int cp0 = cg * 16;
    float pv[16];
    #pragma unroll
    for (int p = 0; p < 16; p++)
        pv[p] = vbase[(size_t)cp0 * 2 * HW + goff[p]];

    for (int cp = cp0; cp < cp0 + 16; cp++) {
        __syncthreads();  // readers of Vs done (and At ready on first iter)
        #pragma unroll
        for (int p = 0; p < 16; p++)
            Vs[jj[p] * 68 + kk_[p]] = pv[p];   // row = j token, col = channel (BUGFIX)
        __syncthreads();
        if (cp + 1 < cp0 + 16) {
            #pragma unroll
            for (int p = 0; p < 16; p++)
                pv[p] = vbase[(size_t)(cp + 1) * 2 * HW + goff[p]];
        }
        float c00=0,c01=0,c02=0,c03=0, c10=0,c11=0,c12=0,c13=0;
        float c20=0,c21=0,c22=0,c23=0, c30=0,c31=0,c32=0,c33=0;
        #pragma unroll 8
        for (int kk = 0; kk < 64; kk++) {
            float4 av = At4[kk * 17 + ti];
            float4 vv = Vs4[kk * 17 + tj];
            c00 += av.x*vv.x; c01 += av.x*vv.y; c02 += av.x*vv.z; c03 += av.x*vv.w;
            c10 += av.y*vv.x; c11 += av.y*vv.y; c12 += av.y*vv.z; c13 += av.y*vv.w;
            c20 += av.z*vv.x; c21 += av.z*vv.y; c22 += av.z*vv.z; c23 += av.z*vv.w;
            c30 += av.w*vv.x; c31 += av.w*vv.y; c32 += av.w*vv.z; c33 += av.w*vv.w;
        }
        int cc0 = tj * 4, chp = cc0 >> 5, col0 = cc0 & 31;
        size_t cbase = (size_t)(cp * 2 + chp) * HW;
        float4 rows[4] = { make_float4(c00,c01,c02,c03), make_float4(c10,c11,c12,c13),
                           make_float4(c20,c21,c22,c23), make_float4(c30,c31,c32,c33) };
        #pragma unroll
        for (int ii = 0; ii < 4; ii++) {
            int t = ti * 4 + ii;
            int y = (t >> 3) * 32 + yoff;
            int xx = (t & 7) * 32 + col0;
            *(float4*)&ob[cbase + y * 256 + xx] = rows[ii];
        }
    }
}

// ===========================================================================
// K5: 1x1 projection + bias. Block = 128 positions; 8-out x 4-pos tiles.
// ===========================================================================
__global__ __launch_bounds__(256) void k5_proj(
    const float* __restrict__ wp, const float* __restrict__ bp,
    float* __restrict__ out)
{
    float* Ws = dsm;             // [64 c][68] (o contiguous)
    float* Xs = Ws + 64 * 68;    // [64 c][132] (p contiguous)
    const int blk = blockIdx.x;  // 8192 = 16 b * 256 y * 2 xh
    const int b = blk >> 9;
    const int rem = blk & 511;
    const int y = rem >> 1, x0 = (rem & 1) << 7;
    const int tid = threadIdx.x, to = tid >> 5, tp = tid & 31;

    const float* ib = g_av + (size_t)b * 64 * HW + y * 256 + x0;
    for (int idx = tid; idx < 4096; idx += 256) {
        int o = idx >> 6, c = idx & 63;          // coalesced read in c
        Ws[c * 68 + o] = wp[o * 64 + c];
    }
    #pragma unroll
    for (int p = 0; p < 32; p++) {
        int idx = tid + p * 256;
        int c = idx >> 7, px = idx & 127;
        Xs[c * 132 + px] = ib[(size_t)c * HW + px];
    }
    __syncthreads();

    const float4* Ws4 = (const float4*)Ws;
    const float4* Xs4 = (const float4*)Xs;
    float a0x=0,a0y=0,a0z=0,a0w=0, a1x=0,a1y=0,a1z=0,a1w=0;
    float a2x=0,a2y=0,a2z=0,a2w=0, a3x=0,a3y=0,a3z=0,a3w=0;
    float a4x=0,a4y=0,a4z=0,a4w=0, a5x=0,a5y=0,a5z=0,a5w=0;
    float a6x=0,a6y=0,a6z=0,a6w=0, a7x=0,a7y=0,a7z=0,a7w=0;
    #pragma unroll 8
    for (int c = 0; c < 64; c++) {
        float4 w0 = Ws4[c * 17 + to * 2];
        float4 w1 = Ws4[c * 17 + to * 2 + 1];
        float4 xv = Xs4[c * 33 + tp];
        a0x += w0.x*xv.x; a0y += w0.x*xv.y; a0z += w0.x*xv.z; a0w += w0.x*xv.w;
        a1x += w0.y*xv.x; a1y += w0.y*xv.y; a1z += w0.y*xv.z; a1w += w0.y*xv.w;
        a2x += w0.z*xv.x; a2y += w0.z*xv.y; a2z += w0.z*xv.z; a2w += w0.z*xv.w;
        a3x += w0.w*xv.x; a3y += w0.w*xv.y; a3z += w0.w*xv.z; a3w += w0.w*xv.w;
        a4x += w1.x*xv.x; a4y += w1.x*xv.y; a4z += w1.x*xv.z; a4w += w1.x*xv.w;
        a5x += w1.y*xv.x; a5y += w1.y*xv.y; a5z += w1.y*xv.z; a5w += w1.y*xv.w;
        a6x += w1.z*xv.x; a6y += w1.z*xv.y; a6z += w1.z*xv.z; a6w += w1.z*xv.w;
        a7x += w1.w*xv.x; a7y += w1.w*xv.y; a7z += w1.w*xv.z; a7w += w1.w*xv.w;
    }
    float* op = out + (size_t)b * 64 * HW + y * 256 + x0 + tp * 4;
    const int ob8 = to * 8;
    float4 res[8] = { make_float4(a0x,a0y,a0z,a0w), make_float4(a1x,a1y,a1z,a1w),
                      make_float4(a2x,a2y,a2z,a2w), make_float4(a3x,a3y,a3z,a3w),
                      make_float4(a4x,a4y,a4z,a4w), make_float4(a5x,a5y,a5z,a5w),
                      make_float4(a6x,a6y,a6z,a6w), make_float4(a7x,a7y,a7z,a7w) };
    #pragma unroll
    for (int rr = 0; rr < 8; rr++) {
        float bb = bp[ob8 + rr];
        float4 v = res[rr];
        v.x += bb; v.y += bb; v.z += bb; v.w += bb;
        *(float4*)&op[(size_t)(ob8 + rr) * HW] = v;
    }
}

// ===========================================================================
extern "C" void kernel_launch(void* const* d_in, const int* in_sizes, int n_in,
                              void* d_out, int out_size)
{
    const float* x     = (const float*)d_in[0];
    const float* wqkv  = (const float*)d_in[1];
    const float* wdw   = (const float*)d_in[2];
    const float* wproj = (const float*)d_in[3];
    const float* bproj = (const float*)d_in[4];
    const float* pos   = (const float*)d_in[5];
    float* out = (float*)d_out;

    const int smem1 = (64 * HPAD + OC * HPAD + 64 * OC + OC * 9) * 4;  // 160,960 B
    const int smem5 = (64 * 68 + 64 * 132) * 4;                        // 51,200 B
    cudaFuncSetAttribute(k1_qkv_dw, cudaFuncAttributeMaxDynamicSharedMemorySize, smem1);
    cudaFuncSetAttribute(k5_proj,   cudaFuncAttributeMaxDynamicSharedMemorySize, smem5);

    k1_qkv_dw<<<dim3(16, 16, 16), 512, smem1>>>(x, wqkv, wdw);
    k2_sim<<<1024, 256>>>();
    k3_softmax<<<2048, 128>>>(pos);
    k4_av<<<1024, 256>>>();
    k5_proj<<<8192, 256, smem5>>>(wproj, bproj, out);
}